// round 1
// baseline (speedup 1.0000x reference)
#include <cuda_runtime.h>
#include <math.h>
#include <stdint.h>

// Problem constants
#define B_   2
#define T_   1024
#define E_   2048
#define H_   16
#define G_   4
#define HS_  128
#define L_   4
#define V_   32000
#define FF_  8192
#define NTOK (B_ * T_)          // 2048
#define QKV_OUT ((H_ + 2*G_) * HS_)  // 3072

// ----------------------------------------------------------------------------
// Scratch (device globals; no allocation allowed)
// ----------------------------------------------------------------------------
__device__ float g_x[NTOK * E_];        // residual stream
__device__ float g_xn[NTOK * E_];       // normed activations
__device__ float g_qkv[NTOK * QKV_OUT]; // qkv projections
__device__ float g_h[NTOK * FF_];       // mlp hidden
__device__ float g_y[NTOK * E_];        // attention output
__device__ float g_cos[T_ * (HS_/2)];   // rope cache
__device__ float g_sin[T_ * (HS_/2)];

// ----------------------------------------------------------------------------
// Embedding gather
// ----------------------------------------------------------------------------
__global__ void embed_kernel(const int* __restrict__ idx,
                             const float* __restrict__ wte,
                             float* __restrict__ x) {
    int row = blockIdx.x;                 // token row [0, NTOK)
    int tok = idx[row];
    const float* src = wte + (size_t)tok * E_;
    float* dst = x + (size_t)row * E_;
    for (int e = threadIdx.x; e < E_; e += blockDim.x) dst[e] = src[e];
}

// ----------------------------------------------------------------------------
// RoPE cache (fp64 for angle precision)
// ----------------------------------------------------------------------------
__global__ void rope_table_kernel(float* __restrict__ ctab, float* __restrict__ stab) {
    int i = blockIdx.x * blockDim.x + threadIdx.x;
    if (i >= T_ * (HS_/2)) return;
    int t = i / (HS_/2);
    int d = i % (HS_/2);
    double inv = pow(10000.0, -(double)(2 * d) / (double)HS_);
    double a = (double)t * inv;
    ctab[i] = (float)cos(a);
    stab[i] = (float)sin(a);
}

// ----------------------------------------------------------------------------
// RoPE apply (in-place on q and k slices of qkv)
// ----------------------------------------------------------------------------
__global__ void rope_apply_kernel(float* __restrict__ qkv,
                                  const float* __restrict__ ctab,
                                  const float* __restrict__ stab) {
    int row = blockIdx.x;                // token row
    int tt = row % T_;                   // position in sequence
    float* base_row = qkv + (size_t)row * QKV_OUT;
    const int NPAIR = (H_ + G_) * (HS_/2);   // 20 * 64 = 1280
    for (int p = threadIdx.x; p < NPAIR; p += blockDim.x) {
        int u = p >> 6;        // head/group unit 0..19
        int d = p & 63;        // rotation pair index
        int base = (u < H_) ? u * HS_ : H_ * HS_ + (u - H_) * HS_;
        float* ptr = base_row + base;
        float c = ctab[tt * (HS_/2) + d];
        float s = stab[tt * (HS_/2) + d];
        float x1 = ptr[d];
        float x2 = ptr[d + HS_/2];
        ptr[d]         = x1 * c - x2 * s;
        ptr[d + HS_/2] = x2 * c + x1 * s;
    }
}

// ----------------------------------------------------------------------------
// RMSNorm: one block per token row
// ----------------------------------------------------------------------------
__global__ void rmsnorm_kernel(const float* __restrict__ x,
                               const float* __restrict__ w,
                               float* __restrict__ out) {
    __shared__ float red[32];
    int row = blockIdx.x;
    const float* xr = x + (size_t)row * E_;
    float* orow = out + (size_t)row * E_;

    float ss = 0.f;
    for (int e = threadIdx.x; e < E_; e += blockDim.x) {
        float v = xr[e];
        ss += v * v;
    }
    // block reduce sum
    int lane = threadIdx.x & 31, wrp = threadIdx.x >> 5;
    #pragma unroll
    for (int o = 16; o; o >>= 1) ss += __shfl_xor_sync(0xffffffffu, ss, o);
    if (lane == 0) red[wrp] = ss;
    __syncthreads();
    int nw = blockDim.x >> 5;
    float tot = (threadIdx.x < nw) ? red[threadIdx.x] : 0.f;
    if (wrp == 0) {
        #pragma unroll
        for (int o = 16; o; o >>= 1) tot += __shfl_xor_sync(0xffffffffu, tot, o);
        if (lane == 0) red[0] = tot;
    }
    __syncthreads();
    float scale = rsqrtf(red[0] / (float)E_ + 1e-5f);
    for (int e = threadIdx.x; e < E_; e += blockDim.x)
        orow[e] = xr[e] * scale * w[e];
}

// ----------------------------------------------------------------------------
// SGEMM: C[M,N] = A[M,K] * B[N,K]^T   (both operands K-contiguous, "NT")
// 128x128 block tile, BK=8, 256 threads, 8x8 per-thread micro-tile.
// mode 0: store, 1: tanh-gelu, 2: add residual (res[r*N+c])
// Requires M%128==0, N%128==0, K%8==0.
// ----------------------------------------------------------------------------
#define BM 128
#define BN 128
#define BK 8

__device__ __forceinline__ float gelu_tanh(float v) {
    float v3 = v * v * v;
    return 0.5f * v * (1.f + tanhf(0.7978845608028654f * (v + 0.044715f * v3)));
}

__global__ __launch_bounds__(256, 2)
void sgemm_nt_kernel(const float* __restrict__ A,
                     const float* __restrict__ B,
                     float* __restrict__ C,
                     const float* __restrict__ res,
                     int M, int N, int K, int mode) {
    __shared__ float As[BK][BM];
    __shared__ float Bs[BK][BN];

    int tid = threadIdx.x;
    int brow = blockIdx.y * BM;
    int bcol = blockIdx.x * BN;

    int tx = tid & 15;        // 16 thread-cols * 8 = 128
    int ty = tid >> 4;        // 16 thread-rows * 8 = 128

    // global->smem load mapping: 256 threads, each one float4
    int ld_row = tid >> 1;           // 0..127
    int ld_col = (tid & 1) * 4;      // 0 or 4

    const float* Aptr = A + (size_t)(brow + ld_row) * K + ld_col;
    const float* Bptr = B + (size_t)(bcol + ld_row) * K + ld_col;

    float acc[8][8];
    #pragma unroll
    for (int i = 0; i < 8; i++)
        #pragma unroll
        for (int j = 0; j < 8; j++) acc[i][j] = 0.f;

    for (int k0 = 0; k0 < K; k0 += BK) {
        float4 av = *(const float4*)(Aptr + k0);
        float4 bv = *(const float4*)(Bptr + k0);
        As[ld_col + 0][ld_row] = av.x;
        As[ld_col + 1][ld_row] = av.y;
        As[ld_col + 2][ld_row] = av.z;
        As[ld_col + 3][ld_row] = av.w;
        Bs[ld_col + 0][ld_row] = bv.x;
        Bs[ld_col + 1][ld_row] = bv.y;
        Bs[ld_col + 2][ld_row] = bv.z;
        Bs[ld_col + 3][ld_row] = bv.w;
        __syncthreads();

        #pragma unroll
        for (int kk = 0; kk < BK; kk++) {
            float4 a0 = *(const float4*)&As[kk][ty * 8];
            float4 a1 = *(const float4*)&As[kk][ty * 8 + 4];
            float4 b0 = *(const float4*)&Bs[kk][tx * 8];
            float4 b1 = *(const float4*)&Bs[kk][tx * 8 + 4];
            float ar[8] = {a0.x, a0.y, a0.z, a0.w, a1.x, a1.y, a1.z, a1.w};
            float br[8] = {b0.x, b0.y, b0.z, b0.w, b1.x, b1.y, b1.z, b1.w};
            #pragma unroll
            for (int i = 0; i < 8; i++)
                #pragma unroll
                for (int j = 0; j < 8; j++)
                    acc[i][j] = fmaf(ar[i], br[j], acc[i][j]);
        }
        __syncthreads();
    }

    // epilogue
    #pragma unroll
    for (int i = 0; i < 8; i++) {
        int r = brow + ty * 8 + i;
        float* crow = C + (size_t)r * N + bcol + tx * 8;
        const float* rrow = res ? (res + (size_t)r * N + bcol + tx * 8) : nullptr;
        #pragma unroll
        for (int j = 0; j < 8; j++) {
            float v = acc[i][j];
            if (mode == 1)      v = gelu_tanh(v);
            else if (mode == 2) v += rrow[j];
            crow[j] = v;
        }
    }
}

// ----------------------------------------------------------------------------
// Attention: one block per (t, h, b), 128 threads. Two-pass softmax.
// q/k/v live inside g_qkv (after RoPE): q at f=h*128, k at 2048+g*128, v at 2560+g*128
// ----------------------------------------------------------------------------
__global__ __launch_bounds__(128)
void attn_kernel(const float* __restrict__ qkv, float* __restrict__ y) {
    __shared__ float sc[T_];
    __shared__ float qs[HS_];
    __shared__ float red[32];

    int t = blockIdx.x;
    int h = blockIdx.y;
    int b = blockIdx.z;
    int tid = threadIdx.x;

    int row = b * T_ + t;
    const float* qp = qkv + (size_t)row * QKV_OUT + h * HS_;
    qs[tid] = qp[tid];
    __syncthreads();

    int g = h >> 2;  // h / (H/G)
    const float* kb = qkv + (size_t)(b * T_) * QKV_OUT + H_ * HS_ + g * HS_;
    const float* vb = kb + G_ * HS_;
    const float scale = 0.08838834764831845f;  // 1/sqrt(128)

    // pass 1: scores
    for (int s = tid; s <= t; s += 128) {
        const float4* kp = (const float4*)(kb + (size_t)s * QKV_OUT);
        float a = 0.f;
        #pragma unroll
        for (int d4 = 0; d4 < HS_ / 4; d4++) {
            float4 k4 = kp[d4];
            float4 q4 = *(const float4*)&qs[d4 * 4];
            a = fmaf(q4.x, k4.x, a);
            a = fmaf(q4.y, k4.y, a);
            a = fmaf(q4.z, k4.z, a);
            a = fmaf(q4.w, k4.w, a);
        }
        sc[s] = a * scale;
    }
    __syncthreads();

    // max
    float m = -INFINITY;
    for (int s = tid; s <= t; s += 128) m = fmaxf(m, sc[s]);
    int lane = tid & 31, wrp = tid >> 5;
    #pragma unroll
    for (int o = 16; o; o >>= 1) m = fmaxf(m, __shfl_xor_sync(0xffffffffu, m, o));
    if (lane == 0) red[wrp] = m;
    __syncthreads();
    m = (tid < 4) ? red[tid] : -INFINITY;
    if (wrp == 0) {
        #pragma unroll
        for (int o = 2; o; o >>= 1) m = fmaxf(m, __shfl_xor_sync(0xffffffffu, m, o));
        if (lane == 0) red[0] = m;
    }
    __syncthreads();
    m = red[0];
    __syncthreads();

    // exp + sum
    float sum = 0.f;
    for (int s = tid; s <= t; s += 128) {
        float e = expf(sc[s] - m);
        sc[s] = e;
        sum += e;
    }
    #pragma unroll
    for (int o = 16; o; o >>= 1) sum += __shfl_xor_sync(0xffffffffu, sum, o);
    if (lane == 0) red[wrp] = sum;
    __syncthreads();
    sum = (tid < 4) ? red[tid] : 0.f;
    if (wrp == 0) {
        #pragma unroll
        for (int o = 2; o; o >>= 1) sum += __shfl_xor_sync(0xffffffffu, sum, o);
        if (lane == 0) red[0] = sum;
    }
    __syncthreads();
    float inv = 1.f / red[0];
    __syncthreads();

    // pass 2: weighted V sum (thread tid owns dim tid; coalesced V reads)
    float acc = 0.f;
    int s = 0;
    for (; s + 4 <= t + 1; s += 4) {
        float p0 = sc[s + 0], p1 = sc[s + 1], p2 = sc[s + 2], p3 = sc[s + 3];
        acc = fmaf(p0, vb[(size_t)(s + 0) * QKV_OUT + tid], acc);
        acc = fmaf(p1, vb[(size_t)(s + 1) * QKV_OUT + tid], acc);
        acc = fmaf(p2, vb[(size_t)(s + 2) * QKV_OUT + tid], acc);
        acc = fmaf(p3, vb[(size_t)(s + 3) * QKV_OUT + tid], acc);
    }
    for (; s <= t; s++) acc = fmaf(sc[s], vb[(size_t)s * QKV_OUT + tid], acc);

    y[(size_t)row * (H_ * HS_) + h * HS_ + tid] = acc * inv;
}

// ----------------------------------------------------------------------------
// Launch
// ----------------------------------------------------------------------------
static inline void sgemm(const float* A, const float* B, float* C,
                         const float* res, int M, int N, int K, int mode) {
    dim3 grid(N / BN, M / BM);
    sgemm_nt_kernel<<<grid, 256>>>(A, B, C, res, M, N, K, mode);
}

extern "C" void kernel_launch(void* const* d_in, const int* in_sizes, int n_in,
                              void* d_out, int out_size) {
    const int*   idx         = (const int*)  d_in[0];
    const float* wte         = (const float*)d_in[1];
    const float* qkv_w       = (const float*)d_in[2];
    const float* attn_proj_w = (const float*)d_in[3];
    const float* fc_w        = (const float*)d_in[4];
    const float* mlp_proj_w  = (const float*)d_in[5];
    const float* norm1_w     = (const float*)d_in[6];
    const float* norm2_w     = (const float*)d_in[7];
    const float* lnf_w       = (const float*)d_in[8];
    const float* lm_head_w   = (const float*)d_in[9];
    float* out = (float*)d_out;

    float *x, *xn, *qkv, *hbuf, *ybuf, *ctab, *stab;
    cudaGetSymbolAddress((void**)&x,    g_x);
    cudaGetSymbolAddress((void**)&xn,   g_xn);
    cudaGetSymbolAddress((void**)&qkv,  g_qkv);
    cudaGetSymbolAddress((void**)&hbuf, g_h);
    cudaGetSymbolAddress((void**)&ybuf, g_y);
    cudaGetSymbolAddress((void**)&ctab, g_cos);
    cudaGetSymbolAddress((void**)&stab, g_sin);

    // rope cache + embedding
    rope_table_kernel<<<(T_ * (HS_/2) + 255) / 256, 256>>>(ctab, stab);
    embed_kernel<<<NTOK, 256>>>(idx, wte, x);

    for (int l = 0; l < L_; l++) {
        const float* qw  = qkv_w       + (size_t)l * QKV_OUT * E_;
        const float* pw  = attn_proj_w + (size_t)l * E_ * (H_ * HS_);
        const float* fw  = fc_w        + (size_t)l * FF_ * E_;
        const float* mw  = mlp_proj_w  + (size_t)l * E_ * FF_;
        const float* n1  = norm1_w     + (size_t)l * E_;
        const float* n2  = norm2_w     + (size_t)l * E_;

        // attention block
        rmsnorm_kernel<<<NTOK, 256>>>(x, n1, xn);
        sgemm(xn, qw, qkv, nullptr, NTOK, QKV_OUT, E_, 0);
        rope_apply_kernel<<<NTOK, 256>>>(qkv, ctab, stab);
        {
            dim3 grid(T_, H_, B_);
            attn_kernel<<<grid, 128>>>(qkv, ybuf);
        }
        sgemm(ybuf, pw, x, x, NTOK, E_, H_ * HS_, 2);   // x += y @ Wp^T

        // mlp block
        rmsnorm_kernel<<<NTOK, 256>>>(x, n2, xn);
        sgemm(xn, fw, hbuf, nullptr, NTOK, FF_, E_, 1); // gelu fused
        sgemm(hbuf, mw, x, x, NTOK, E_, FF_, 2);        // x += h @ Wm^T
    }

    // final norm + lm head
    rmsnorm_kernel<<<NTOK, 256>>>(x, lnf_w, xn);
    sgemm(xn, lm_head_w, out, nullptr, NTOK, V_, E_, 0);
}

// round 3
// speedup vs baseline: 1.0015x; 1.0015x over previous
#include <cuda_runtime.h>
#include <math.h>
#include <stdint.h>

// Problem constants
#define B_   2
#define T_   1024
#define E_   2048
#define H_   16
#define G_   4
#define HS_  128
#define L_   4
#define V_   32000
#define FF_  8192
#define NTOK (B_ * T_)          // 2048
#define QKV_OUT ((H_ + 2*G_) * HS_)  // 3072

// ----------------------------------------------------------------------------
// Scratch (device globals; no allocation allowed)
// ----------------------------------------------------------------------------
__device__ float g_x[NTOK * E_];        // residual stream
__device__ float g_xn[NTOK * E_];       // normed activations
__device__ float g_qkv[NTOK * QKV_OUT]; // qkv projections
__device__ float g_h[NTOK * FF_];       // mlp hidden
__device__ float g_y[NTOK * E_];        // attention output
__device__ float g_cos[T_ * (HS_/2)];   // rope cache
__device__ float g_sin[T_ * (HS_/2)];

// ----------------------------------------------------------------------------
// Embedding gather
// ----------------------------------------------------------------------------
__global__ void embed_kernel(const int* __restrict__ idx,
                             const float* __restrict__ wte,
                             float* __restrict__ x) {
    int row = blockIdx.x;                 // token row [0, NTOK)
    int tok = idx[row];
    const float* src = wte + (size_t)tok * E_;
    float* dst = x + (size_t)row * E_;
    for (int e = threadIdx.x; e < E_; e += blockDim.x) dst[e] = src[e];
}

// ----------------------------------------------------------------------------
// RoPE cache (fp64 for angle precision)
// ----------------------------------------------------------------------------
__global__ void rope_table_kernel(float* __restrict__ ctab, float* __restrict__ stab) {
    int i = blockIdx.x * blockDim.x + threadIdx.x;
    if (i >= T_ * (HS_/2)) return;
    int t = i / (HS_/2);
    int d = i % (HS_/2);
    double inv = pow(10000.0, -(double)(2 * d) / (double)HS_);
    double a = (double)t * inv;
    ctab[i] = (float)cos(a);
    stab[i] = (float)sin(a);
}

// ----------------------------------------------------------------------------
// RoPE apply (in-place on q and k slices of qkv)
// ----------------------------------------------------------------------------
__global__ void rope_apply_kernel(float* __restrict__ qkv,
                                  const float* __restrict__ ctab,
                                  const float* __restrict__ stab) {
    int row = blockIdx.x;                // token row
    int tt = row % T_;                   // position in sequence
    float* base_row = qkv + (size_t)row * QKV_OUT;
    const int NPAIR = (H_ + G_) * (HS_/2);   // 20 * 64 = 1280
    for (int p = threadIdx.x; p < NPAIR; p += blockDim.x) {
        int u = p >> 6;        // head/group unit 0..19
        int d = p & 63;        // rotation pair index
        int base = (u < H_) ? u * HS_ : H_ * HS_ + (u - H_) * HS_;
        float* ptr = base_row + base;
        float c = ctab[tt * (HS_/2) + d];
        float s = stab[tt * (HS_/2) + d];
        float x1 = ptr[d];
        float x2 = ptr[d + HS_/2];
        ptr[d]         = x1 * c - x2 * s;
        ptr[d + HS_/2] = x2 * c + x1 * s;
    }
}

// ----------------------------------------------------------------------------
// RMSNorm: one block per token row
// ----------------------------------------------------------------------------
__global__ void rmsnorm_kernel(const float* __restrict__ x,
                               const float* __restrict__ w,
                               float* __restrict__ out) {
    __shared__ float red[32];
    int row = blockIdx.x;
    const float* xr = x + (size_t)row * E_;
    float* orow = out + (size_t)row * E_;

    float ss = 0.f;
    for (int e = threadIdx.x; e < E_; e += blockDim.x) {
        float v = xr[e];
        ss += v * v;
    }
    // block reduce sum
    int lane = threadIdx.x & 31, wrp = threadIdx.x >> 5;
    #pragma unroll
    for (int o = 16; o; o >>= 1) ss += __shfl_xor_sync(0xffffffffu, ss, o);
    if (lane == 0) red[wrp] = ss;
    __syncthreads();
    int nw = blockDim.x >> 5;
    float tot = (threadIdx.x < nw) ? red[threadIdx.x] : 0.f;
    if (wrp == 0) {
        #pragma unroll
        for (int o = 16; o; o >>= 1) tot += __shfl_xor_sync(0xffffffffu, tot, o);
        if (lane == 0) red[0] = tot;
    }
    __syncthreads();
    float scale = rsqrtf(red[0] / (float)E_ + 1e-5f);
    for (int e = threadIdx.x; e < E_; e += blockDim.x)
        orow[e] = xr[e] * scale * w[e];
}

// ----------------------------------------------------------------------------
// SGEMM: C[M,N] = A[M,K] * B[N,K]^T   (both operands K-contiguous, "NT")
// 128x128 block tile, BK=8, 256 threads, 8x8 per-thread micro-tile.
// mode 0: store, 1: tanh-gelu, 2: add residual (res[r*N+c])
// Requires M%128==0, N%128==0, K%8==0.
// ----------------------------------------------------------------------------
#define BM 128
#define BN 128
#define BK 8

__device__ __forceinline__ float gelu_tanh(float v) {
    float v3 = v * v * v;
    return 0.5f * v * (1.f + tanhf(0.7978845608028654f * (v + 0.044715f * v3)));
}

__global__ __launch_bounds__(256, 2)
void sgemm_nt_kernel(const float* __restrict__ A,
                     const float* __restrict__ B,
                     float* __restrict__ C,
                     const float* __restrict__ res,
                     int M, int N, int K, int mode) {
    __shared__ float As[BK][BM];
    __shared__ float Bs[BK][BN];

    int tid = threadIdx.x;
    int brow = blockIdx.y * BM;
    int bcol = blockIdx.x * BN;

    int tx = tid & 15;        // 16 thread-cols * 8 = 128
    int ty = tid >> 4;        // 16 thread-rows * 8 = 128

    // global->smem load mapping: 256 threads, each one float4
    int ld_row = tid >> 1;           // 0..127
    int ld_col = (tid & 1) * 4;      // 0 or 4

    const float* Aptr = A + (size_t)(brow + ld_row) * K + ld_col;
    const float* Bptr = B + (size_t)(bcol + ld_row) * K + ld_col;

    float acc[8][8];
    #pragma unroll
    for (int i = 0; i < 8; i++)
        #pragma unroll
        for (int j = 0; j < 8; j++) acc[i][j] = 0.f;

    for (int k0 = 0; k0 < K; k0 += BK) {
        float4 av = *(const float4*)(Aptr + k0);
        float4 bv = *(const float4*)(Bptr + k0);
        As[ld_col + 0][ld_row] = av.x;
        As[ld_col + 1][ld_row] = av.y;
        As[ld_col + 2][ld_row] = av.z;
        As[ld_col + 3][ld_row] = av.w;
        Bs[ld_col + 0][ld_row] = bv.x;
        Bs[ld_col + 1][ld_row] = bv.y;
        Bs[ld_col + 2][ld_row] = bv.z;
        Bs[ld_col + 3][ld_row] = bv.w;
        __syncthreads();

        #pragma unroll
        for (int kk = 0; kk < BK; kk++) {
            float4 a0 = *(const float4*)&As[kk][ty * 8];
            float4 a1 = *(const float4*)&As[kk][ty * 8 + 4];
            float4 b0 = *(const float4*)&Bs[kk][tx * 8];
            float4 b1 = *(const float4*)&Bs[kk][tx * 8 + 4];
            float ar[8] = {a0.x, a0.y, a0.z, a0.w, a1.x, a1.y, a1.z, a1.w};
            float br[8] = {b0.x, b0.y, b0.z, b0.w, b1.x, b1.y, b1.z, b1.w};
            #pragma unroll
            for (int i = 0; i < 8; i++)
                #pragma unroll
                for (int j = 0; j < 8; j++)
                    acc[i][j] = fmaf(ar[i], br[j], acc[i][j]);
        }
        __syncthreads();
    }

    // epilogue
    #pragma unroll
    for (int i = 0; i < 8; i++) {
        int r = brow + ty * 8 + i;
        float* crow = C + (size_t)r * N + bcol + tx * 8;
        const float* rrow = res ? (res + (size_t)r * N + bcol + tx * 8) : nullptr;
        #pragma unroll
        for (int j = 0; j < 8; j++) {
            float v = acc[i][j];
            if (mode == 1)      v = gelu_tanh(v);
            else if (mode == 2) v += rrow[j];
            crow[j] = v;
        }
    }
}

// ----------------------------------------------------------------------------
// Attention: one block per (t, h, b), 128 threads. Two-pass softmax.
// q/k/v live inside g_qkv (after RoPE): q at f=h*128, k at 2048+g*128, v at 2560+g*128
// ----------------------------------------------------------------------------
__global__ __launch_bounds__(128)
void attn_kernel(const float* __restrict__ qkv, float* __restrict__ y) {
    __shared__ float sc[T_];
    __shared__ float qs[HS_];
    __shared__ float red[32];

    int t = blockIdx.x;
    int h = blockIdx.y;
    int b = blockIdx.z;
    int tid = threadIdx.x;

    int row = b * T_ + t;
    const float* qp = qkv + (size_t)row * QKV_OUT + h * HS_;
    qs[tid] = qp[tid];
    __syncthreads();

    int g = h >> 2;  // h / (H/G)
    const float* kb = qkv + (size_t)(b * T_) * QKV_OUT + H_ * HS_ + g * HS_;
    const float* vb = kb + G_ * HS_;
    const float scale = 0.08838834764831845f;  // 1/sqrt(128)

    // pass 1: scores
    for (int s = tid; s <= t; s += 128) {
        const float4* kp = (const float4*)(kb + (size_t)s * QKV_OUT);
        float a = 0.f;
        #pragma unroll
        for (int d4 = 0; d4 < HS_ / 4; d4++) {
            float4 k4 = kp[d4];
            float4 q4 = *(const float4*)&qs[d4 * 4];
            a = fmaf(q4.x, k4.x, a);
            a = fmaf(q4.y, k4.y, a);
            a = fmaf(q4.z, k4.z, a);
            a = fmaf(q4.w, k4.w, a);
        }
        sc[s] = a * scale;
    }
    __syncthreads();

    // max
    float m = -INFINITY;
    for (int s = tid; s <= t; s += 128) m = fmaxf(m, sc[s]);
    int lane = tid & 31, wrp = tid >> 5;
    #pragma unroll
    for (int o = 16; o; o >>= 1) m = fmaxf(m, __shfl_xor_sync(0xffffffffu, m, o));
    if (lane == 0) red[wrp] = m;
    __syncthreads();
    m = (tid < 4) ? red[tid] : -INFINITY;
    if (wrp == 0) {
        #pragma unroll
        for (int o = 2; o; o >>= 1) m = fmaxf(m, __shfl_xor_sync(0xffffffffu, m, o));
        if (lane == 0) red[0] = m;
    }
    __syncthreads();
    m = red[0];
    __syncthreads();

    // exp + sum
    float sum = 0.f;
    for (int s = tid; s <= t; s += 128) {
        float e = expf(sc[s] - m);
        sc[s] = e;
        sum += e;
    }
    #pragma unroll
    for (int o = 16; o; o >>= 1) sum += __shfl_xor_sync(0xffffffffu, sum, o);
    if (lane == 0) red[wrp] = sum;
    __syncthreads();
    sum = (tid < 4) ? red[tid] : 0.f;
    if (wrp == 0) {
        #pragma unroll
        for (int o = 2; o; o >>= 1) sum += __shfl_xor_sync(0xffffffffu, sum, o);
        if (lane == 0) red[0] = sum;
    }
    __syncthreads();
    float inv = 1.f / red[0];
    __syncthreads();

    // pass 2: weighted V sum (thread tid owns dim tid; coalesced V reads)
    float acc = 0.f;
    int s = 0;
    for (; s + 4 <= t + 1; s += 4) {
        float p0 = sc[s + 0], p1 = sc[s + 1], p2 = sc[s + 2], p3 = sc[s + 3];
        acc = fmaf(p0, vb[(size_t)(s + 0) * QKV_OUT + tid], acc);
        acc = fmaf(p1, vb[(size_t)(s + 1) * QKV_OUT + tid], acc);
        acc = fmaf(p2, vb[(size_t)(s + 2) * QKV_OUT + tid], acc);
        acc = fmaf(p3, vb[(size_t)(s + 3) * QKV_OUT + tid], acc);
    }
    for (; s <= t; s++) acc = fmaf(sc[s], vb[(size_t)s * QKV_OUT + tid], acc);

    y[(size_t)row * (H_ * HS_) + h * HS_ + tid] = acc * inv;
}

// ----------------------------------------------------------------------------
// Launch
// ----------------------------------------------------------------------------
static inline void sgemm(const float* A, const float* B, float* C,
                         const float* res, int M, int N, int K, int mode) {
    dim3 grid(N / BN, M / BM);
    sgemm_nt_kernel<<<grid, 256>>>(A, B, C, res, M, N, K, mode);
}

extern "C" void kernel_launch(void* const* d_in, const int* in_sizes, int n_in,
                              void* d_out, int out_size) {
    const int*   idx         = (const int*)  d_in[0];
    const float* wte         = (const float*)d_in[1];
    const float* qkv_w       = (const float*)d_in[2];
    const float* attn_proj_w = (const float*)d_in[3];
    const float* fc_w        = (const float*)d_in[4];
    const float* mlp_proj_w  = (const float*)d_in[5];
    const float* norm1_w     = (const float*)d_in[6];
    const float* norm2_w     = (const float*)d_in[7];
    const float* lnf_w       = (const float*)d_in[8];
    const float* lm_head_w   = (const float*)d_in[9];
    float* out = (float*)d_out;

    float *x, *xn, *qkv, *hbuf, *ybuf, *ctab, *stab;
    cudaGetSymbolAddress((void**)&x,    g_x);
    cudaGetSymbolAddress((void**)&xn,   g_xn);
    cudaGetSymbolAddress((void**)&qkv,  g_qkv);
    cudaGetSymbolAddress((void**)&hbuf, g_h);
    cudaGetSymbolAddress((void**)&ybuf, g_y);
    cudaGetSymbolAddress((void**)&ctab, g_cos);
    cudaGetSymbolAddress((void**)&stab, g_sin);

    // rope cache + embedding
    rope_table_kernel<<<(T_ * (HS_/2) + 255) / 256, 256>>>(ctab, stab);
    embed_kernel<<<NTOK, 256>>>(idx, wte, x);

    for (int l = 0; l < L_; l++) {
        const float* qw  = qkv_w       + (size_t)l * QKV_OUT * E_;
        const float* pw  = attn_proj_w + (size_t)l * E_ * (H_ * HS_);
        const float* fw  = fc_w        + (size_t)l * FF_ * E_;
        const float* mw  = mlp_proj_w  + (size_t)l * E_ * FF_;
        const float* n1  = norm1_w     + (size_t)l * E_;
        const float* n2  = norm2_w     + (size_t)l * E_;

        // attention block
        rmsnorm_kernel<<<NTOK, 256>>>(x, n1, xn);
        sgemm(xn, qw, qkv, nullptr, NTOK, QKV_OUT, E_, 0);
        rope_apply_kernel<<<NTOK, 256>>>(qkv, ctab, stab);
        {
            dim3 grid(T_, H_, B_);
            attn_kernel<<<grid, 128>>>(qkv, ybuf);
        }
        sgemm(ybuf, pw, x, x, NTOK, E_, H_ * HS_, 2);   // x += y @ Wp^T

        // mlp block
        rmsnorm_kernel<<<NTOK, 256>>>(x, n2, xn);
        sgemm(xn, fw, hbuf, nullptr, NTOK, FF_, E_, 1); // gelu fused
        sgemm(hbuf, mw, x, x, NTOK, E_, FF_, 2);        // x += h @ Wm^T
    }

    // final norm + lm head
    rmsnorm_kernel<<<NTOK, 256>>>(x, lnf_w, xn);
    sgemm(xn, lm_head_w, out, nullptr, NTOK, V_, E_, 0);
}

// round 4
// speedup vs baseline: 1.0018x; 1.0003x over previous
#include <cuda_runtime.h>
#include <math.h>
#include <stdint.h>

// Problem constants
#define B_   2
#define T_   1024
#define E_   2048
#define H_   16
#define G_   4
#define HS_  128
#define L_   4
#define V_   32000
#define FF_  8192
#define NTOK (B_ * T_)          // 2048
#define QKV_OUT ((H_ + 2*G_) * HS_)  // 3072

// ----------------------------------------------------------------------------
// Scratch (device globals; no allocation allowed)
// ----------------------------------------------------------------------------
__device__ float g_x[NTOK * E_];        // residual stream
__device__ float g_xn[NTOK * E_];       // normed activations
__device__ float g_qkv[NTOK * QKV_OUT]; // qkv projections
__device__ float g_h[NTOK * FF_];       // mlp hidden
__device__ float g_y[NTOK * E_];        // attention output
__device__ float g_cos[T_ * (HS_/2)];   // rope cache
__device__ float g_sin[T_ * (HS_/2)];

// ----------------------------------------------------------------------------
// Embedding gather
// ----------------------------------------------------------------------------
__global__ void embed_kernel(const int* __restrict__ idx,
                             const float* __restrict__ wte,
                             float* __restrict__ x) {
    int row = blockIdx.x;                 // token row [0, NTOK)
    int tok = idx[row];
    const float* src = wte + (size_t)tok * E_;
    float* dst = x + (size_t)row * E_;
    for (int e = threadIdx.x; e < E_; e += blockDim.x) dst[e] = src[e];
}

// ----------------------------------------------------------------------------
// RoPE cache (fp64 for angle precision)
// ----------------------------------------------------------------------------
__global__ void rope_table_kernel(float* __restrict__ ctab, float* __restrict__ stab) {
    int i = blockIdx.x * blockDim.x + threadIdx.x;
    if (i >= T_ * (HS_/2)) return;
    int t = i / (HS_/2);
    int d = i % (HS_/2);
    double inv = pow(10000.0, -(double)(2 * d) / (double)HS_);
    double a = (double)t * inv;
    ctab[i] = (float)cos(a);
    stab[i] = (float)sin(a);
}

// ----------------------------------------------------------------------------
// RoPE apply (in-place on q and k slices of qkv)
// ----------------------------------------------------------------------------
__global__ void rope_apply_kernel(float* __restrict__ qkv,
                                  const float* __restrict__ ctab,
                                  const float* __restrict__ stab) {
    int row = blockIdx.x;                // token row
    int tt = row % T_;                   // position in sequence
    float* base_row = qkv + (size_t)row * QKV_OUT;
    const int NPAIR = (H_ + G_) * (HS_/2);   // 20 * 64 = 1280
    for (int p = threadIdx.x; p < NPAIR; p += blockDim.x) {
        int u = p >> 6;        // head/group unit 0..19
        int d = p & 63;        // rotation pair index
        int base = (u < H_) ? u * HS_ : H_ * HS_ + (u - H_) * HS_;
        float* ptr = base_row + base;
        float c = ctab[tt * (HS_/2) + d];
        float s = stab[tt * (HS_/2) + d];
        float x1 = ptr[d];
        float x2 = ptr[d + HS_/2];
        ptr[d]         = x1 * c - x2 * s;
        ptr[d + HS_/2] = x2 * c + x1 * s;
    }
}

// ----------------------------------------------------------------------------
// RMSNorm: one block per token row
// ----------------------------------------------------------------------------
__global__ void rmsnorm_kernel(const float* __restrict__ x,
                               const float* __restrict__ w,
                               float* __restrict__ out) {
    __shared__ float red[32];
    int row = blockIdx.x;
    const float* xr = x + (size_t)row * E_;
    float* orow = out + (size_t)row * E_;

    float ss = 0.f;
    for (int e = threadIdx.x; e < E_; e += blockDim.x) {
        float v = xr[e];
        ss += v * v;
    }
    // block reduce sum
    int lane = threadIdx.x & 31, wrp = threadIdx.x >> 5;
    #pragma unroll
    for (int o = 16; o; o >>= 1) ss += __shfl_xor_sync(0xffffffffu, ss, o);
    if (lane == 0) red[wrp] = ss;
    __syncthreads();
    int nw = blockDim.x >> 5;
    float tot = (threadIdx.x < nw) ? red[threadIdx.x] : 0.f;
    if (wrp == 0) {
        #pragma unroll
        for (int o = 16; o; o >>= 1) tot += __shfl_xor_sync(0xffffffffu, tot, o);
        if (lane == 0) red[0] = tot;
    }
    __syncthreads();
    float scale = rsqrtf(red[0] / (float)E_ + 1e-5f);
    for (int e = threadIdx.x; e < E_; e += blockDim.x)
        orow[e] = xr[e] * scale * w[e];
}

// ----------------------------------------------------------------------------
// SGEMM: C[M,N] = A[M,K] * B[N,K]^T   (both operands K-contiguous, "NT")
// 128x128 block tile, BK=8, 256 threads, 8x8 per-thread micro-tile.
// mode 0: store, 1: tanh-gelu, 2: add residual (res[r*N+c])
// Requires M%128==0, N%128==0, K%8==0.
// ----------------------------------------------------------------------------
#define BM 128
#define BN 128
#define BK 8

__device__ __forceinline__ float gelu_tanh(float v) {
    float v3 = v * v * v;
    return 0.5f * v * (1.f + tanhf(0.7978845608028654f * (v + 0.044715f * v3)));
}

__global__ __launch_bounds__(256, 2)
void sgemm_nt_kernel(const float* __restrict__ A,
                     const float* __restrict__ B,
                     float* __restrict__ C,
                     const float* __restrict__ res,
                     int M, int N, int K, int mode) {
    __shared__ float As[BK][BM];
    __shared__ float Bs[BK][BN];

    int tid = threadIdx.x;
    int brow = blockIdx.y * BM;
    int bcol = blockIdx.x * BN;

    int tx = tid & 15;        // 16 thread-cols * 8 = 128
    int ty = tid >> 4;        // 16 thread-rows * 8 = 128

    // global->smem load mapping: 256 threads, each one float4
    int ld_row = tid >> 1;           // 0..127
    int ld_col = (tid & 1) * 4;      // 0 or 4

    const float* Aptr = A + (size_t)(brow + ld_row) * K + ld_col;
    const float* Bptr = B + (size_t)(bcol + ld_row) * K + ld_col;

    float acc[8][8];
    #pragma unroll
    for (int i = 0; i < 8; i++)
        #pragma unroll
        for (int j = 0; j < 8; j++) acc[i][j] = 0.f;

    for (int k0 = 0; k0 < K; k0 += BK) {
        float4 av = *(const float4*)(Aptr + k0);
        float4 bv = *(const float4*)(Bptr + k0);
        As[ld_col + 0][ld_row] = av.x;
        As[ld_col + 1][ld_row] = av.y;
        As[ld_col + 2][ld_row] = av.z;
        As[ld_col + 3][ld_row] = av.w;
        Bs[ld_col + 0][ld_row] = bv.x;
        Bs[ld_col + 1][ld_row] = bv.y;
        Bs[ld_col + 2][ld_row] = bv.z;
        Bs[ld_col + 3][ld_row] = bv.w;
        __syncthreads();

        #pragma unroll
        for (int kk = 0; kk < BK; kk++) {
            float4 a0 = *(const float4*)&As[kk][ty * 8];
            float4 a1 = *(const float4*)&As[kk][ty * 8 + 4];
            float4 b0 = *(const float4*)&Bs[kk][tx * 8];
            float4 b1 = *(const float4*)&Bs[kk][tx * 8 + 4];
            float ar[8] = {a0.x, a0.y, a0.z, a0.w, a1.x, a1.y, a1.z, a1.w};
            float br[8] = {b0.x, b0.y, b0.z, b0.w, b1.x, b1.y, b1.z, b1.w};
            #pragma unroll
            for (int i = 0; i < 8; i++)
                #pragma unroll
                for (int j = 0; j < 8; j++)
                    acc[i][j] = fmaf(ar[i], br[j], acc[i][j]);
        }
        __syncthreads();
    }

    // epilogue
    #pragma unroll
    for (int i = 0; i < 8; i++) {
        int r = brow + ty * 8 + i;
        float* crow = C + (size_t)r * N + bcol + tx * 8;
        const float* rrow = res ? (res + (size_t)r * N + bcol + tx * 8) : nullptr;
        #pragma unroll
        for (int j = 0; j < 8; j++) {
            float v = acc[i][j];
            if (mode == 1)      v = gelu_tanh(v);
            else if (mode == 2) v += rrow[j];
            crow[j] = v;
        }
    }
}

// ----------------------------------------------------------------------------
// Attention: one block per (t, h, b), 128 threads. Two-pass softmax.
// q/k/v live inside g_qkv (after RoPE): q at f=h*128, k at 2048+g*128, v at 2560+g*128
// ----------------------------------------------------------------------------
__global__ __launch_bounds__(128)
void attn_kernel(const float* __restrict__ qkv, float* __restrict__ y) {
    __shared__ float sc[T_];
    __shared__ float qs[HS_];
    __shared__ float red[32];

    int t = blockIdx.x;
    int h = blockIdx.y;
    int b = blockIdx.z;
    int tid = threadIdx.x;

    int row = b * T_ + t;
    const float* qp = qkv + (size_t)row * QKV_OUT + h * HS_;
    qs[tid] = qp[tid];
    __syncthreads();

    int g = h >> 2;  // h / (H/G)
    const float* kb = qkv + (size_t)(b * T_) * QKV_OUT + H_ * HS_ + g * HS_;
    const float* vb = kb + G_ * HS_;
    const float scale = 0.08838834764831845f;  // 1/sqrt(128)

    // pass 1: scores
    for (int s = tid; s <= t; s += 128) {
        const float4* kp = (const float4*)(kb + (size_t)s * QKV_OUT);
        float a = 0.f;
        #pragma unroll
        for (int d4 = 0; d4 < HS_ / 4; d4++) {
            float4 k4 = kp[d4];
            float4 q4 = *(const float4*)&qs[d4 * 4];
            a = fmaf(q4.x, k4.x, a);
            a = fmaf(q4.y, k4.y, a);
            a = fmaf(q4.z, k4.z, a);
            a = fmaf(q4.w, k4.w, a);
        }
        sc[s] = a * scale;
    }
    __syncthreads();

    // max
    float m = -INFINITY;
    for (int s = tid; s <= t; s += 128) m = fmaxf(m, sc[s]);
    int lane = tid & 31, wrp = tid >> 5;
    #pragma unroll
    for (int o = 16; o; o >>= 1) m = fmaxf(m, __shfl_xor_sync(0xffffffffu, m, o));
    if (lane == 0) red[wrp] = m;
    __syncthreads();
    m = (tid < 4) ? red[tid] : -INFINITY;
    if (wrp == 0) {
        #pragma unroll
        for (int o = 2; o; o >>= 1) m = fmaxf(m, __shfl_xor_sync(0xffffffffu, m, o));
        if (lane == 0) red[0] = m;
    }
    __syncthreads();
    m = red[0];
    __syncthreads();

    // exp + sum
    float sum = 0.f;
    for (int s = tid; s <= t; s += 128) {
        float e = expf(sc[s] - m);
        sc[s] = e;
        sum += e;
    }
    #pragma unroll
    for (int o = 16; o; o >>= 1) sum += __shfl_xor_sync(0xffffffffu, sum, o);
    if (lane == 0) red[wrp] = sum;
    __syncthreads();
    sum = (tid < 4) ? red[tid] : 0.f;
    if (wrp == 0) {
        #pragma unroll
        for (int o = 2; o; o >>= 1) sum += __shfl_xor_sync(0xffffffffu, sum, o);
        if (lane == 0) red[0] = sum;
    }
    __syncthreads();
    float inv = 1.f / red[0];
    __syncthreads();

    // pass 2: weighted V sum (thread tid owns dim tid; coalesced V reads)
    float acc = 0.f;
    int s = 0;
    for (; s + 4 <= t + 1; s += 4) {
        float p0 = sc[s + 0], p1 = sc[s + 1], p2 = sc[s + 2], p3 = sc[s + 3];
        acc = fmaf(p0, vb[(size_t)(s + 0) * QKV_OUT + tid], acc);
        acc = fmaf(p1, vb[(size_t)(s + 1) * QKV_OUT + tid], acc);
        acc = fmaf(p2, vb[(size_t)(s + 2) * QKV_OUT + tid], acc);
        acc = fmaf(p3, vb[(size_t)(s + 3) * QKV_OUT + tid], acc);
    }
    for (; s <= t; s++) acc = fmaf(sc[s], vb[(size_t)s * QKV_OUT + tid], acc);

    y[(size_t)row * (H_ * HS_) + h * HS_ + tid] = acc * inv;
}

// ----------------------------------------------------------------------------
// Launch
// ----------------------------------------------------------------------------
static inline void sgemm(const float* A, const float* B, float* C,
                         const float* res, int M, int N, int K, int mode) {
    dim3 grid(N / BN, M / BM);
    sgemm_nt_kernel<<<grid, 256>>>(A, B, C, res, M, N, K, mode);
}

extern "C" void kernel_launch(void* const* d_in, const int* in_sizes, int n_in,
                              void* d_out, int out_size) {
    const int*   idx         = (const int*)  d_in[0];
    const float* wte         = (const float*)d_in[1];
    const float* qkv_w       = (const float*)d_in[2];
    const float* attn_proj_w = (const float*)d_in[3];
    const float* fc_w        = (const float*)d_in[4];
    const float* mlp_proj_w  = (const float*)d_in[5];
    const float* norm1_w     = (const float*)d_in[6];
    const float* norm2_w     = (const float*)d_in[7];
    const float* lnf_w       = (const float*)d_in[8];
    const float* lm_head_w   = (const float*)d_in[9];
    float* out = (float*)d_out;

    float *x, *xn, *qkv, *hbuf, *ybuf, *ctab, *stab;
    cudaGetSymbolAddress((void**)&x,    g_x);
    cudaGetSymbolAddress((void**)&xn,   g_xn);
    cudaGetSymbolAddress((void**)&qkv,  g_qkv);
    cudaGetSymbolAddress((void**)&hbuf, g_h);
    cudaGetSymbolAddress((void**)&ybuf, g_y);
    cudaGetSymbolAddress((void**)&ctab, g_cos);
    cudaGetSymbolAddress((void**)&stab, g_sin);

    // rope cache + embedding
    rope_table_kernel<<<(T_ * (HS_/2) + 255) / 256, 256>>>(ctab, stab);
    embed_kernel<<<NTOK, 256>>>(idx, wte, x);

    for (int l = 0; l < L_; l++) {
        const float* qw  = qkv_w       + (size_t)l * QKV_OUT * E_;
        const float* pw  = attn_proj_w + (size_t)l * E_ * (H_ * HS_);
        const float* fw  = fc_w        + (size_t)l * FF_ * E_;
        const float* mw  = mlp_proj_w  + (size_t)l * E_ * FF_;
        const float* n1  = norm1_w     + (size_t)l * E_;
        const float* n2  = norm2_w     + (size_t)l * E_;

        // attention block
        rmsnorm_kernel<<<NTOK, 256>>>(x, n1, xn);
        sgemm(xn, qw, qkv, nullptr, NTOK, QKV_OUT, E_, 0);
        rope_apply_kernel<<<NTOK, 256>>>(qkv, ctab, stab);
        {
            dim3 grid(T_, H_, B_);
            attn_kernel<<<grid, 128>>>(qkv, ybuf);
        }
        sgemm(ybuf, pw, x, x, NTOK, E_, H_ * HS_, 2);   // x += y @ Wp^T

        // mlp block
        rmsnorm_kernel<<<NTOK, 256>>>(x, n2, xn);
        sgemm(xn, fw, hbuf, nullptr, NTOK, FF_, E_, 1); // gelu fused
        sgemm(hbuf, mw, x, x, NTOK, E_, FF_, 2);        // x += h @ Wm^T
    }

    // final norm + lm head
    rmsnorm_kernel<<<NTOK, 256>>>(x, lnf_w, xn);
    sgemm(xn, lm_head_w, out, nullptr, NTOK, V_, E_, 0);
}